// round 12
// baseline (speedup 1.0000x reference)
#include <cuda_runtime.h>
#include <math.h>

#define N_NODES 8192
#define E_EDGES 262144
#define E_TOT   (E_EDGES + N_NODES)   // 270336, with self loops
#define IN_CH   256
#define HEADS   8
#define CPH     32
#define HC      256                    // HEADS*CPH
#define VLEN    (N_NODES * HC)         // 2097152
#define NEG_SLOPE 0.2f

// ---------------- device scratch (no allocations allowed) ----------------
__device__ float g_xh[N_NODES * HC];        // projected features [n, h*c]
__device__ float g_asrc[N_NODES * HEADS];
__device__ float g_adst[N_NODES * HEADS];
__device__ int   g_deg[N_NODES];
__device__ int   g_fill[N_NODES];
__device__ int   g_rowptr[N_NODES + 1];
__device__ int   g_csrc[E_TOT];
__device__ float g_y[CPH];                  // output logits (atomic accum)

// ---------------- packed f32x2 helpers (Blackwell FFMA2) ----------------
__device__ __forceinline__ unsigned long long pk2(float lo, float hi) {
    unsigned long long r;
    asm("mov.b64 %0, {%1, %2};" : "=l"(r) : "f"(lo), "f"(hi));
    return r;
}
__device__ __forceinline__ void upk2(unsigned long long v, float& lo, float& hi) {
    asm("mov.b64 {%0, %1}, %2;" : "=f"(lo), "=f"(hi) : "l"(v));
}
__device__ __forceinline__ void fma2(unsigned long long& d,
                                     unsigned long long a, unsigned long long b) {
    asm("fma.rn.f32x2 %0, %1, %2, %3;" : "=l"(d) : "l"(a), "l"(b), "l"(d));
}

// ---------------- K0: init scratch ----------------
__global__ void k_zero() {
    int i = blockIdx.x * blockDim.x + threadIdx.x;
    if (i < N_NODES) { g_deg[i] = 1; g_fill[i] = 0; }  // deg=1: self loop pre-counted
    if (i < CPH) g_y[i] = 0.f;
}

// ---------------- K1: GEMM xh = x @ lin_w^T ----------------
// 64x64 tile, BK=16, 256 threads, 4x4 per thread, k-major smem, FFMA2 core.
__global__ __launch_bounds__(256) void k_gemm(const float* __restrict__ x,
                                              const float* __restrict__ w) {
    __shared__ __align__(16) float As[16 * 68];   // [k][m], stride 68
    __shared__ __align__(16) float Bs[16 * 68];   // [k][n]
    int tid = threadIdx.x;
    int tx = tid & 15, ty = tid >> 4;
    int m0 = blockIdx.x * 64;
    int n0 = blockIdx.y * 64;

    unsigned long long acc2[4][2];
#pragma unroll
    for (int i = 0; i < 4; i++) { acc2[i][0] = 0ull; acc2[i][1] = 0ull; }

    int lrow = tid >> 2;            // 0..63 (m or n within tile)
    int lcol = (tid & 3) * 4;       // k sub-offset 0,4,8,12

    for (int k0 = 0; k0 < IN_CH; k0 += 16) {
        float4 av = *(const float4*)&x[(size_t)(m0 + lrow) * IN_CH + k0 + lcol];
        float4 bv = *(const float4*)&w[(size_t)(n0 + lrow) * IN_CH + k0 + lcol];
        As[(lcol + 0) * 68 + lrow] = av.x; As[(lcol + 1) * 68 + lrow] = av.y;
        As[(lcol + 2) * 68 + lrow] = av.z; As[(lcol + 3) * 68 + lrow] = av.w;
        Bs[(lcol + 0) * 68 + lrow] = bv.x; Bs[(lcol + 1) * 68 + lrow] = bv.y;
        Bs[(lcol + 2) * 68 + lrow] = bv.z; Bs[(lcol + 3) * 68 + lrow] = bv.w;
        __syncthreads();
#pragma unroll
        for (int k = 0; k < 16; k++) {
            float4 a4 = *(const float4*)&As[k * 68 + ty * 4];
            float4 b4 = *(const float4*)&Bs[k * 68 + tx * 4];
            unsigned long long b2lo = pk2(b4.x, b4.y);
            unsigned long long b2hi = pk2(b4.z, b4.w);
            unsigned long long a0 = pk2(a4.x, a4.x);
            unsigned long long a1 = pk2(a4.y, a4.y);
            unsigned long long a2 = pk2(a4.z, a4.z);
            unsigned long long a3 = pk2(a4.w, a4.w);
            fma2(acc2[0][0], a0, b2lo); fma2(acc2[0][1], a0, b2hi);
            fma2(acc2[1][0], a1, b2lo); fma2(acc2[1][1], a1, b2hi);
            fma2(acc2[2][0], a2, b2lo); fma2(acc2[2][1], a2, b2hi);
            fma2(acc2[3][0], a3, b2lo); fma2(acc2[3][1], a3, b2hi);
        }
        __syncthreads();
    }
#pragma unroll
    for (int i = 0; i < 4; i++) {
        float4 o;
        upk2(acc2[i][0], o.x, o.y);
        upk2(acc2[i][1], o.z, o.w);
        *(float4*)&g_xh[(size_t)(m0 + ty * 4 + i) * HC + n0 + tx * 4] = o;
    }
}

// ---------------- K2: per-node attention scalars ----------------
__global__ __launch_bounds__(256) void k_attvec(const float* __restrict__ att_src,
                                                const float* __restrict__ att_dst) {
    int n = blockIdx.x;
    int h = threadIdx.x >> 5;
    int c = threadIdx.x & 31;
    float v = g_xh[(size_t)n * HC + h * CPH + c];
    float s1 = v * att_src[h * CPH + c];
    float s2 = v * att_dst[h * CPH + c];
#pragma unroll
    for (int off = 16; off; off >>= 1) {
        s1 += __shfl_down_sync(0xffffffffu, s1, off);
        s2 += __shfl_down_sync(0xffffffffu, s2, off);
    }
    if (c == 0) { g_asrc[n * HEADS + h] = s1; g_adst[n * HEADS + h] = s2; }
}

// ---------------- K3a: degree histogram (1 edge/thread, fire-and-forget RED) ----------------
__global__ void k_degree(const int* __restrict__ ei) {
    int e = blockIdx.x * blockDim.x + threadIdx.x;   // E_EDGES threads
    atomicAdd(&g_deg[ei[E_EDGES + e]], 1);
}

// ---------------- K3b: exclusive scan (single block, 1024 thr x 8) ----------------
__global__ __launch_bounds__(1024) void k_scan() {
    __shared__ int sh[1024];
    int t = threadIdx.x;
    int loc[8];
    int s = 0;
#pragma unroll
    for (int i = 0; i < 8; i++) { loc[i] = s; s += g_deg[t * 8 + i]; }
    sh[t] = s;
    __syncthreads();
    for (int off = 1; off < 1024; off <<= 1) {
        int v = (t >= off) ? sh[t - off] : 0;
        __syncthreads();
        sh[t] += v;
        __syncthreads();
    }
    int base = (t == 0) ? 0 : sh[t - 1];
#pragma unroll
    for (int i = 0; i < 8; i++) g_rowptr[t * 8 + i] = base + loc[i];
    if (t == 1023) g_rowptr[N_NODES] = sh[1023];
}

// ---------------- K3c: scatter src ids into CSR (vectorized + self loops) ----------------
#define SCAT_EDGE_BLOCKS (E_EDGES / 4 / 256)   // 256
__global__ void k_scatter(const int* __restrict__ ei) {
    if (blockIdx.x < SCAT_EDGE_BLOCKS) {
        int t = blockIdx.x * blockDim.x + threadIdx.x;
        int4 sv = *(const int4*)&ei[t * 4];
        int4 dv = *(const int4*)&ei[E_EDGES + t * 4];
        g_csrc[g_rowptr[dv.x] + atomicAdd(&g_fill[dv.x], 1)] = sv.x;
        g_csrc[g_rowptr[dv.y] + atomicAdd(&g_fill[dv.y], 1)] = sv.y;
        g_csrc[g_rowptr[dv.z] + atomicAdd(&g_fill[dv.z], 1)] = sv.z;
        g_csrc[g_rowptr[dv.w] + atomicAdd(&g_fill[dv.w], 1)] = sv.w;
    } else {
        int i = (blockIdx.x - SCAT_EDGE_BLOCKS) * blockDim.x + threadIdx.x;
        if (i < N_NODES)
            g_csrc[g_rowptr[i] + atomicAdd(&g_fill[i], 1)] = i;   // self loop
    }
}

// ---------------- K4: fused softmax + aggregation + OUTPUT MATVEC ----------------
// Block i, warp h: head h of node i (gather phase, unchanged from R11).
// Epilogue: block i's 256 v-values (in smem) dot the contiguous 32KB slice
// out_w[:, i*256:(i+1)*256]; warp h handles output channels {h, h+8, h+16, h+24};
// one atomicAdd per (block, channel). g_v eliminated; matvec kernel eliminated;
// the L2-gather phase of some blocks overlaps the DRAM-stream phase of others.
__global__ __launch_bounds__(256) void k_agg(const float* __restrict__ bias,
                                             const float* __restrict__ out_w) {
    int i = blockIdx.x;
    int lane = threadIdx.x & 31;
    int h = threadIdx.x >> 5;
    int beg = g_rowptr[i], end = g_rowptr[i + 1];
    const float* __restrict__ xh = g_xh;
    int off = h * CPH + lane;   // == threadIdx.x

    float adst_h = g_adst[i * HEADS + h];
    float acc = 0.f, ds = 0.f;

    for (int base = beg; base < end; base += 32) {
        int e = base + lane;
        int j = 0;
        float alpha = 0.f;
        if (e < end) {
            j = g_csrc[e];
            float v = g_asrc[j * HEADS + h] + adst_h;
            v = v > 0.f ? v : NEG_SLOPE * v;
            alpha = __expf(v);
            ds += alpha;
        }
        int nn = min(32, end - base);
        int t = 0;
        for (; t + 8 <= nn; t += 8) {
            float a0 = __shfl_sync(0xffffffffu, alpha, t + 0);
            float a1 = __shfl_sync(0xffffffffu, alpha, t + 1);
            float a2 = __shfl_sync(0xffffffffu, alpha, t + 2);
            float a3 = __shfl_sync(0xffffffffu, alpha, t + 3);
            float a4 = __shfl_sync(0xffffffffu, alpha, t + 4);
            float a5 = __shfl_sync(0xffffffffu, alpha, t + 5);
            float a6 = __shfl_sync(0xffffffffu, alpha, t + 6);
            float a7 = __shfl_sync(0xffffffffu, alpha, t + 7);
            int j0 = __shfl_sync(0xffffffffu, j, t + 0);
            int j1 = __shfl_sync(0xffffffffu, j, t + 1);
            int j2 = __shfl_sync(0xffffffffu, j, t + 2);
            int j3 = __shfl_sync(0xffffffffu, j, t + 3);
            int j4 = __shfl_sync(0xffffffffu, j, t + 4);
            int j5 = __shfl_sync(0xffffffffu, j, t + 5);
            int j6 = __shfl_sync(0xffffffffu, j, t + 6);
            int j7 = __shfl_sync(0xffffffffu, j, t + 7);
            float x0 = xh[(size_t)j0 * HC + off];
            float x1 = xh[(size_t)j1 * HC + off];
            float x2 = xh[(size_t)j2 * HC + off];
            float x3 = xh[(size_t)j3 * HC + off];
            float x4 = xh[(size_t)j4 * HC + off];
            float x5 = xh[(size_t)j5 * HC + off];
            float x6 = xh[(size_t)j6 * HC + off];
            float x7 = xh[(size_t)j7 * HC + off];
            acc = fmaf(a0, x0, acc); acc = fmaf(a1, x1, acc);
            acc = fmaf(a2, x2, acc); acc = fmaf(a3, x3, acc);
            acc = fmaf(a4, x4, acc); acc = fmaf(a5, x5, acc);
            acc = fmaf(a6, x6, acc); acc = fmaf(a7, x7, acc);
        }
        for (; t < nn; t++) {
            float a = __shfl_sync(0xffffffffu, alpha, t);
            int jj  = __shfl_sync(0xffffffffu, j, t);
            acc = fmaf(a, xh[(size_t)jj * HC + off], acc);
        }
    }
#pragma unroll
    for (int off2 = 16; off2; off2 >>= 1)
        ds += __shfl_xor_sync(0xffffffffu, ds, off2);
    float dinv = 1.f / ds;

    // ---- epilogue: stage v-chunk in smem, dot with out_w slice ----
    __shared__ __align__(16) float sv[HC];
    sv[off] = fmaf(acc, dinv, bias[off]);
    __syncthreads();

    const float4* sv4 = (const float4*)sv;
    float4 va = sv4[lane];          // bytes 16*lane
    float4 vb = sv4[lane + 32];     // second half
#pragma unroll
    for (int cc = 0; cc < 4; cc++) {
        int c = (cc << 3) | h;      // warp h -> channels h, h+8, h+16, h+24
        const float4* w4 = (const float4*)(out_w + (size_t)c * VLEN + (size_t)i * HC);
        float4 wa = w4[lane];
        float4 wb = w4[lane + 32];
        float p = 0.f;
        p = fmaf(wa.x, va.x, p); p = fmaf(wa.y, va.y, p);
        p = fmaf(wa.z, va.z, p); p = fmaf(wa.w, va.w, p);
        p = fmaf(wb.x, vb.x, p); p = fmaf(wb.y, vb.y, p);
        p = fmaf(wb.z, vb.z, p); p = fmaf(wb.w, vb.w, p);
#pragma unroll
        for (int o = 16; o; o >>= 1) p += __shfl_down_sync(0xffffffffu, p, o);
        if (lane == 0) atomicAdd(&g_y[c], p);
    }
}

// ---------------- K6: softmax over 32 logits ----------------
__global__ void k_softmax(const float* __restrict__ out_b, float* __restrict__ out) {
    int t = threadIdx.x;  // 32 threads
    float v = g_y[t] + out_b[t];
    float mx = v;
#pragma unroll
    for (int off = 16; off; off >>= 1) mx = fmaxf(mx, __shfl_xor_sync(0xffffffffu, mx, off));
    float e = expf(v - mx);
    float ssum = e;
#pragma unroll
    for (int off = 16; off; off >>= 1) ssum += __shfl_xor_sync(0xffffffffu, ssum, off);
    out[t] = e / ssum;
}

// ---------------- launch ----------------
extern "C" void kernel_launch(void* const* d_in, const int* in_sizes, int n_in,
                              void* d_out, int out_size) {
    const float* x       = (const float*)d_in[0];
    const int*   ei      = (const int*)d_in[1];
    const float* lin_w   = (const float*)d_in[2];
    const float* att_src = (const float*)d_in[3];
    const float* att_dst = (const float*)d_in[4];
    const float* bias    = (const float*)d_in[5];
    const float* out_w   = (const float*)d_in[6];
    const float* out_b   = (const float*)d_in[7];
    float* out = (float*)d_out;

    k_zero<<<(N_NODES + 255) / 256, 256>>>();
    k_gemm<<<dim3(N_NODES / 64, HC / 64), 256>>>(x, lin_w);
    k_attvec<<<N_NODES, 256>>>(att_src, att_dst);
    k_degree<<<E_EDGES / 256, 256>>>(ei);
    k_scan<<<1, 1024>>>();
    k_scatter<<<SCAT_EDGE_BLOCKS + (N_NODES + 255) / 256, 256>>>(ei);
    k_agg<<<N_NODES, 256>>>(bias, out_w);
    k_softmax<<<1, 32>>>(out_b, out);
}

// round 13
// speedup vs baseline: 2.0362x; 2.0362x over previous
#include <cuda_runtime.h>
#include <math.h>

#define N_NODES 8192
#define E_EDGES 262144
#define IN_CH   256
#define HEADS   8
#define CPH     32
#define HC      256                    // HEADS*CPH
#define VLEN    (N_NODES * HC)         // 2097152
#define NEG_SLOPE 0.2f
#define ELL_W   128                    // max degree slot count (mean 32, max ~57)

// ---------------- device scratch (no allocations allowed) ----------------
__device__ float g_xh[N_NODES * HC];        // projected features [n, h*c]
__device__ float g_asrc[N_NODES * HEADS];
__device__ float g_adst[N_NODES * HEADS];
__device__ int   g_fill[N_NODES];
__device__ int   g_ell[N_NODES * ELL_W];    // ELL adjacency (src ids per dst)
__device__ float g_y[CPH];                  // output logits (atomic accum)

// ---------------- packed f32x2 helpers (Blackwell FFMA2) ----------------
__device__ __forceinline__ unsigned long long pk2(float lo, float hi) {
    unsigned long long r;
    asm("mov.b64 %0, {%1, %2};" : "=l"(r) : "f"(lo), "f"(hi));
    return r;
}
__device__ __forceinline__ void upk2(unsigned long long v, float& lo, float& hi) {
    asm("mov.b64 {%0, %1}, %2;" : "=f"(lo), "=f"(hi) : "l"(v));
}
__device__ __forceinline__ void fma2(unsigned long long& d,
                                     unsigned long long a, unsigned long long b) {
    asm("fma.rn.f32x2 %0, %1, %2, %3;" : "=l"(d) : "l"(a), "l"(b), "l"(d));
}

// ---------------- K0: init scratch (self loop pre-seeded in ELL slot 0) ----------------
__global__ void k_zero() {
    int i = blockIdx.x * blockDim.x + threadIdx.x;
    if (i < N_NODES) { g_fill[i] = 1; g_ell[i * ELL_W] = i; }
    if (i < CPH) g_y[i] = 0.f;
}

// ---------------- K1: GEMM xh = x @ lin_w^T ----------------
// 64x64 tile, BK=16, 256 threads, 4x4 per thread, k-major smem, FFMA2 core.
__global__ __launch_bounds__(256) void k_gemm(const float* __restrict__ x,
                                              const float* __restrict__ w) {
    __shared__ __align__(16) float As[16 * 68];   // [k][m], stride 68
    __shared__ __align__(16) float Bs[16 * 68];   // [k][n]
    int tid = threadIdx.x;
    int tx = tid & 15, ty = tid >> 4;
    int m0 = blockIdx.x * 64;
    int n0 = blockIdx.y * 64;

    unsigned long long acc2[4][2];
#pragma unroll
    for (int i = 0; i < 4; i++) { acc2[i][0] = 0ull; acc2[i][1] = 0ull; }

    int lrow = tid >> 2;            // 0..63 (m or n within tile)
    int lcol = (tid & 3) * 4;       // k sub-offset 0,4,8,12

    for (int k0 = 0; k0 < IN_CH; k0 += 16) {
        float4 av = *(const float4*)&x[(size_t)(m0 + lrow) * IN_CH + k0 + lcol];
        float4 bv = *(const float4*)&w[(size_t)(n0 + lrow) * IN_CH + k0 + lcol];
        As[(lcol + 0) * 68 + lrow] = av.x; As[(lcol + 1) * 68 + lrow] = av.y;
        As[(lcol + 2) * 68 + lrow] = av.z; As[(lcol + 3) * 68 + lrow] = av.w;
        Bs[(lcol + 0) * 68 + lrow] = bv.x; Bs[(lcol + 1) * 68 + lrow] = bv.y;
        Bs[(lcol + 2) * 68 + lrow] = bv.z; Bs[(lcol + 3) * 68 + lrow] = bv.w;
        __syncthreads();
#pragma unroll
        for (int k = 0; k < 16; k++) {
            float4 a4 = *(const float4*)&As[k * 68 + ty * 4];
            float4 b4 = *(const float4*)&Bs[k * 68 + tx * 4];
            unsigned long long b2lo = pk2(b4.x, b4.y);
            unsigned long long b2hi = pk2(b4.z, b4.w);
            unsigned long long a0 = pk2(a4.x, a4.x);
            unsigned long long a1 = pk2(a4.y, a4.y);
            unsigned long long a2 = pk2(a4.z, a4.z);
            unsigned long long a3 = pk2(a4.w, a4.w);
            fma2(acc2[0][0], a0, b2lo); fma2(acc2[0][1], a0, b2hi);
            fma2(acc2[1][0], a1, b2lo); fma2(acc2[1][1], a1, b2hi);
            fma2(acc2[2][0], a2, b2lo); fma2(acc2[2][1], a2, b2hi);
            fma2(acc2[3][0], a3, b2lo); fma2(acc2[3][1], a3, b2hi);
        }
        __syncthreads();
    }
#pragma unroll
    for (int i = 0; i < 4; i++) {
        float4 o;
        upk2(acc2[i][0], o.x, o.y);
        upk2(acc2[i][1], o.z, o.w);
        *(float4*)&g_xh[(size_t)(m0 + ty * 4 + i) * HC + n0 + tx * 4] = o;
    }
}

// ---------------- K2: per-node attention scalars ----------------
__global__ __launch_bounds__(256) void k_attvec(const float* __restrict__ att_src,
                                                const float* __restrict__ att_dst) {
    int n = blockIdx.x;
    int h = threadIdx.x >> 5;
    int c = threadIdx.x & 31;
    float v = g_xh[(size_t)n * HC + h * CPH + c];
    float s1 = v * att_src[h * CPH + c];
    float s2 = v * att_dst[h * CPH + c];
#pragma unroll
    for (int off = 16; off; off >>= 1) {
        s1 += __shfl_down_sync(0xffffffffu, s1, off);
        s2 += __shfl_down_sync(0xffffffffu, s2, off);
    }
    if (c == 0) { g_asrc[n * HEADS + h] = s1; g_adst[n * HEADS + h] = s2; }
}

// ---------------- K3: direct ELL scatter (no degree/scan needed) ----------------
__global__ void k_scatter(const int* __restrict__ ei) {
    int t = blockIdx.x * blockDim.x + threadIdx.x;   // E_EDGES/4 threads
    int4 sv = *(const int4*)&ei[t * 4];
    int4 dv = *(const int4*)&ei[E_EDGES + t * 4];
    g_ell[dv.x * ELL_W + atomicAdd(&g_fill[dv.x], 1)] = sv.x;
    g_ell[dv.y * ELL_W + atomicAdd(&g_fill[dv.y], 1)] = sv.y;
    g_ell[dv.z * ELL_W + atomicAdd(&g_fill[dv.z], 1)] = sv.z;
    g_ell[dv.w * ELL_W + atomicAdd(&g_fill[dv.w], 1)] = sv.w;
}

// ---------------- K4: fused softmax + aggregation, warp-per-(node,head) ----------------
// Block i, warp h handles head h of node i. Gather loop batched 8-wide (MLP 8).
__global__ __launch_bounds__(256) void k_agg(const float* __restrict__ bias) {
    int i = blockIdx.x;
    int lane = threadIdx.x & 31;
    int h = threadIdx.x >> 5;
    int beg = i * ELL_W, end = beg + g_fill[i];
    const float* __restrict__ xh = g_xh;
    int off = h * CPH + lane;

    float adst_h = g_adst[i * HEADS + h];
    float acc = 0.f, ds = 0.f;

    for (int base = beg; base < end; base += 32) {
        int e = base + lane;
        int j = 0;
        float alpha = 0.f;
        if (e < end) {
            j = g_ell[e];
            float v = g_asrc[j * HEADS + h] + adst_h;
            v = v > 0.f ? v : NEG_SLOPE * v;
            alpha = __expf(v);
            ds += alpha;
        }
        int nn = min(32, end - base);
        int t = 0;
        for (; t + 8 <= nn; t += 8) {
            float a0 = __shfl_sync(0xffffffffu, alpha, t + 0);
            float a1 = __shfl_sync(0xffffffffu, alpha, t + 1);
            float a2 = __shfl_sync(0xffffffffu, alpha, t + 2);
            float a3 = __shfl_sync(0xffffffffu, alpha, t + 3);
            float a4 = __shfl_sync(0xffffffffu, alpha, t + 4);
            float a5 = __shfl_sync(0xffffffffu, alpha, t + 5);
            float a6 = __shfl_sync(0xffffffffu, alpha, t + 6);
            float a7 = __shfl_sync(0xffffffffu, alpha, t + 7);
            int j0 = __shfl_sync(0xffffffffu, j, t + 0);
            int j1 = __shfl_sync(0xffffffffu, j, t + 1);
            int j2 = __shfl_sync(0xffffffffu, j, t + 2);
            int j3 = __shfl_sync(0xffffffffu, j, t + 3);
            int j4 = __shfl_sync(0xffffffffu, j, t + 4);
            int j5 = __shfl_sync(0xffffffffu, j, t + 5);
            int j6 = __shfl_sync(0xffffffffu, j, t + 6);
            int j7 = __shfl_sync(0xffffffffu, j, t + 7);
            float x0 = xh[(size_t)j0 * HC + off];
            float x1 = xh[(size_t)j1 * HC + off];
            float x2 = xh[(size_t)j2 * HC + off];
            float x3 = xh[(size_t)j3 * HC + off];
            float x4 = xh[(size_t)j4 * HC + off];
            float x5 = xh[(size_t)j5 * HC + off];
            float x6 = xh[(size_t)j6 * HC + off];
            float x7 = xh[(size_t)j7 * HC + off];
            acc = fmaf(a0, x0, acc); acc = fmaf(a1, x1, acc);
            acc = fmaf(a2, x2, acc); acc = fmaf(a3, x3, acc);
            acc = fmaf(a4, x4, acc); acc = fmaf(a5, x5, acc);
            acc = fmaf(a6, x6, acc); acc = fmaf(a7, x7, acc);
        }
        for (; t < nn; t++) {
            float a = __shfl_sync(0xffffffffu, alpha, t);
            int jj  = __shfl_sync(0xffffffffu, j, t);
            acc = fmaf(a, xh[(size_t)jj * HC + off], acc);
        }
    }
#pragma unroll
    for (int off2 = 16; off2; off2 >>= 1)
        ds += __shfl_xor_sync(0xffffffffu, ds, off2);
    float dinv = 1.f / ds;
    g_xh[(size_t)0] = g_xh[(size_t)0];   // no-op keep
    // write v into a dedicated buffer region: reuse trick not needed; store to g_v
    // (g_v declared below to keep layout tidy)
    extern __device__ float g_v[];
    g_v[(size_t)i * HC + off] = fmaf(acc, dinv, bias[off]);
}
__device__ float g_v[VLEN];                 // agg + bias, flattened

// ---------------- K5: matvec, warp owns 4 channels exclusively ----------------
#define CHUNK 2048
__global__ __launch_bounds__(256) void k_matvec(const float* __restrict__ out_w) {
    __shared__ __align__(16) float sv[CHUNK];
    int k0 = blockIdx.x * CHUNK;
    int tid = threadIdx.x;
    int lane = tid & 31, wid = tid >> 5;
    const float4* v4 = (const float4*)&g_v[k0];
    float4* sv4 = (float4*)sv;
#pragma unroll
    for (int i = 0; i < CHUNK / 4 / 256; i++) sv4[tid + i * 256] = v4[tid + i * 256];
    __syncthreads();
    const float4* svc = (const float4*)sv;
#pragma unroll
    for (int cc = 0; cc < 4; cc++) {
        int c = wid * 4 + cc;
        const float4* w4 = (const float4*)(out_w + (size_t)c * VLEN + k0);
        float p0 = 0.f, p1 = 0.f;
#pragma unroll
        for (int i = 0; i < 8; i++) {      // 16 float4 per lane, 2-way ILP
            float4 w0 = w4[lane + (2 * i + 0) * 32];
            float4 w1 = w4[lane + (2 * i + 1) * 32];
            float4 v0 = svc[lane + (2 * i + 0) * 32];
            float4 v1 = svc[lane + (2 * i + 1) * 32];
            p0 = fmaf(w0.x, v0.x, p0); p0 = fmaf(w0.y, v0.y, p0);
            p0 = fmaf(w0.z, v0.z, p0); p0 = fmaf(w0.w, v0.w, p0);
            p1 = fmaf(w1.x, v1.x, p1); p1 = fmaf(w1.y, v1.y, p1);
            p1 = fmaf(w1.z, v1.z, p1); p1 = fmaf(w1.w, v1.w, p1);
        }
        float p = p0 + p1;
#pragma unroll
        for (int off = 16; off; off >>= 1) p += __shfl_down_sync(0xffffffffu, p, off);
        if (lane == 0) atomicAdd(&g_y[c], p);
    }
}

// ---------------- K6: softmax over 32 logits ----------------
__global__ void k_softmax(const float* __restrict__ out_b, float* __restrict__ out) {
    int t = threadIdx.x;  // 32 threads
    float v = g_y[t] + out_b[t];
    float mx = v;
#pragma unroll
    for (int off = 16; off; off >>= 1) mx = fmaxf(mx, __shfl_xor_sync(0xffffffffu, mx, off));
    float e = expf(v - mx);
    float ssum = e;
#pragma unroll
    for (int off = 16; off; off >>= 1) ssum += __shfl_xor_sync(0xffffffffu, ssum, off);
    out[t] = e / ssum;
}

// ---------------- launch ----------------
extern "C" void kernel_launch(void* const* d_in, const int* in_sizes, int n_in,
                              void* d_out, int out_size) {
    const float* x       = (const float*)d_in[0];
    const int*   ei      = (const int*)d_in[1];
    const float* lin_w   = (const float*)d_in[2];
    const float* att_src = (const float*)d_in[3];
    const float* att_dst = (const float*)d_in[4];
    const float* bias    = (const float*)d_in[5];
    const float* out_w   = (const float*)d_in[6];
    const float* out_b   = (const float*)d_in[7];
    float* out = (float*)d_out;

    k_zero<<<(N_NODES + 255) / 256, 256>>>();
    k_gemm<<<dim3(N_NODES / 64, HC / 64), 256>>>(x, lin_w);
    k_attvec<<<N_NODES, 256>>>(att_src, att_dst);
    k_scatter<<<E_EDGES / 4 / 256, 256>>>(ei);
    k_agg<<<N_NODES, 256>>>(bias);
    k_matvec<<<VLEN / CHUNK, 256>>>(out_w);
    k_softmax<<<1, 32>>>(out_b, out);
}

// round 15
// speedup vs baseline: 2.1643x; 1.0629x over previous
#include <cuda_runtime.h>
#include <math.h>

#define N_NODES 8192
#define E_EDGES 262144
#define IN_CH   256
#define HEADS   8
#define CPH     32
#define HC      256                    // HEADS*CPH
#define VLEN    (N_NODES * HC)         // 2097152
#define NEG_SLOPE 0.2f
#define ELL_W   128                    // max degree slot count (mean 32, max ~57)

// ---------------- device scratch (no allocations allowed) ----------------
__device__ float g_xh[N_NODES * HC];        // projected features [n, h*c]
__device__ float g_asrc[N_NODES * HEADS];
__device__ float g_adst[N_NODES * HEADS];
__device__ int   g_fill[N_NODES];
__device__ int   g_ell[N_NODES * ELL_W];    // ELL adjacency (src ids per dst)
__device__ float g_v[VLEN];                 // agg + bias, flattened
__device__ float g_y[CPH];                  // output logits (atomic accum)

// ---------------- packed f32x2 helpers (Blackwell FFMA2) ----------------
__device__ __forceinline__ unsigned long long pk2(float lo, float hi) {
    unsigned long long r;
    asm("mov.b64 %0, {%1, %2};" : "=l"(r) : "f"(lo), "f"(hi));
    return r;
}
__device__ __forceinline__ void upk2(unsigned long long v, float& lo, float& hi) {
    asm("mov.b64 {%0, %1}, %2;" : "=f"(lo), "=f"(hi) : "l"(v));
}
__device__ __forceinline__ void fma2(unsigned long long& d,
                                     unsigned long long a, unsigned long long b) {
    asm("fma.rn.f32x2 %0, %1, %2, %3;" : "=l"(d) : "l"(a), "l"(b), "l"(d));
}

// ---------------- K0: init scratch (self loop pre-seeded in ELL slot 0) ----------------
__global__ void k_zero() {
    int i = blockIdx.x * blockDim.x + threadIdx.x;
    if (i < N_NODES) { g_fill[i] = 1; g_ell[i * ELL_W] = i; }
    if (i < CPH) g_y[i] = 0.f;
}

// ---------------- K1: GEMM xh = x @ lin_w^T, attvec fused into epilogue ----------------
// 64x64 tile, BK=16, 256 threads, 4x4 per thread, k-major smem, FFMA2 core.
// Epilogue: block (m0,n0) holds COMPLETE heads h = n0/32, n0/32+1 for 64 nodes.
// For each of a thread's 4 rows, an 8-lane shuffle tree (tx&7 group, offsets
// 4/2/1 — same warp) reduces the 32-channel dot with att_src/att_dst; lane
// tx&7==0 plain-stores a_src/a_dst (each (m,h) owned by exactly one block).
__global__ __launch_bounds__(256) void k_gemm(const float* __restrict__ x,
                                              const float* __restrict__ w,
                                              const float* __restrict__ att_src,
                                              const float* __restrict__ att_dst) {
    __shared__ __align__(16) float As[16 * 68];   // [k][m], stride 68
    __shared__ __align__(16) float Bs[16 * 68];   // [k][n]
    int tid = threadIdx.x;
    int tx = tid & 15, ty = tid >> 4;
    int m0 = blockIdx.x * 64;
    int n0 = blockIdx.y * 64;

    unsigned long long acc2[4][2];
#pragma unroll
    for (int i = 0; i < 4; i++) { acc2[i][0] = 0ull; acc2[i][1] = 0ull; }

    int lrow = tid >> 2;            // 0..63 (m or n within tile)
    int lcol = (tid & 3) * 4;       // k sub-offset 0,4,8,12

    for (int k0 = 0; k0 < IN_CH; k0 += 16) {
        float4 av = *(const float4*)&x[(size_t)(m0 + lrow) * IN_CH + k0 + lcol];
        float4 bv = *(const float4*)&w[(size_t)(n0 + lrow) * IN_CH + k0 + lcol];
        As[(lcol + 0) * 68 + lrow] = av.x; As[(lcol + 1) * 68 + lrow] = av.y;
        As[(lcol + 2) * 68 + lrow] = av.z; As[(lcol + 3) * 68 + lrow] = av.w;
        Bs[(lcol + 0) * 68 + lrow] = bv.x; Bs[(lcol + 1) * 68 + lrow] = bv.y;
        Bs[(lcol + 2) * 68 + lrow] = bv.z; Bs[(lcol + 3) * 68 + lrow] = bv.w;
        __syncthreads();
#pragma unroll
        for (int k = 0; k < 16; k++) {
            float4 a4 = *(const float4*)&As[k * 68 + ty * 4];
            float4 b4 = *(const float4*)&Bs[k * 68 + tx * 4];
            unsigned long long b2lo = pk2(b4.x, b4.y);
            unsigned long long b2hi = pk2(b4.z, b4.w);
            unsigned long long a0 = pk2(a4.x, a4.x);
            unsigned long long a1 = pk2(a4.y, a4.y);
            unsigned long long a2 = pk2(a4.z, a4.z);
            unsigned long long a3 = pk2(a4.w, a4.w);
            fma2(acc2[0][0], a0, b2lo); fma2(acc2[0][1], a0, b2hi);
            fma2(acc2[1][0], a1, b2lo); fma2(acc2[1][1], a1, b2hi);
            fma2(acc2[2][0], a2, b2lo); fma2(acc2[2][1], a2, b2hi);
            fma2(acc2[3][0], a3, b2lo); fma2(acc2[3][1], a3, b2hi);
        }
        __syncthreads();
    }

    // epilogue: write xh tile + fused attention scalars
    int h = (n0 >> 5) + (tx >> 3);                 // global head for this thread's cols
    float4 as4 = ((const float4*)att_src)[h * 8 + (tx & 7)];
    float4 ad4 = ((const float4*)att_dst)[h * 8 + (tx & 7)];
#pragma unroll
    for (int i = 0; i < 4; i++) {
        float4 o;
        upk2(acc2[i][0], o.x, o.y);
        upk2(acc2[i][1], o.z, o.w);
        *(float4*)&g_xh[(size_t)(m0 + ty * 4 + i) * HC + n0 + tx * 4] = o;

        float s1 = o.x * as4.x + o.y * as4.y + o.z * as4.z + o.w * as4.w;
        float s2 = o.x * ad4.x + o.y * ad4.y + o.z * ad4.z + o.w * ad4.w;
#pragma unroll
        for (int off = 4; off; off >>= 1) {
            s1 += __shfl_down_sync(0xffffffffu, s1, off);
            s2 += __shfl_down_sync(0xffffffffu, s2, off);
        }
        if ((tx & 7) == 0) {
            int m = m0 + ty * 4 + i;
            g_asrc[m * HEADS + h] = s1;
            g_adst[m * HEADS + h] = s2;
        }
    }
}

// ---------------- K3: direct ELL scatter (2 edges/thread, grid 512) ----------------
__global__ void k_scatter(const int* __restrict__ ei) {
    int t = blockIdx.x * blockDim.x + threadIdx.x;   // E_EDGES/2 threads
    int2 sv = *(const int2*)&ei[t * 2];
    int2 dv = *(const int2*)&ei[E_EDGES + t * 2];
    g_ell[dv.x * ELL_W + atomicAdd(&g_fill[dv.x], 1)] = sv.x;
    g_ell[dv.y * ELL_W + atomicAdd(&g_fill[dv.y], 1)] = sv.y;
}

// ---------------- K4: fused softmax + aggregation, warp-per-(node,head) ----------------
// Block i, warp h handles head h of node i. Gather loop batched 8-wide (MLP 8).
__global__ __launch_bounds__(256) void k_agg(const float* __restrict__ bias) {
    int i = blockIdx.x;
    int lane = threadIdx.x & 31;
    int h = threadIdx.x >> 5;
    int beg = i * ELL_W, end = beg + g_fill[i];
    const float* __restrict__ xh = g_xh;
    int off = h * CPH + lane;

    float adst_h = g_adst[i * HEADS + h];
    float acc = 0.f, ds = 0.f;

    for (int base = beg; base < end; base += 32) {
        int e = base + lane;
        int j = 0;
        float alpha = 0.f;
        if (e < end) {
            j = g_ell[e];
            float v = g_asrc[j * HEADS + h] + adst_h;
            v = v > 0.f ? v : NEG_SLOPE * v;
            alpha = __expf(v);
            ds += alpha;
        }
        int nn = min(32, end - base);
        int t = 0;
        for (; t + 8 <= nn; t += 8) {
            float a0 = __shfl_sync(0xffffffffu, alpha, t + 0);
            float a1 = __shfl_sync(0xffffffffu, alpha, t + 1);
            float a2 = __shfl_sync(0xffffffffu, alpha, t + 2);
            float a3 = __shfl_sync(0xffffffffu, alpha, t + 3);
            float a4 = __shfl_sync(0xffffffffu, alpha, t + 4);
            float a5 = __shfl_sync(0xffffffffu, alpha, t + 5);
            float a6 = __shfl_sync(0xffffffffu, alpha, t + 6);
            float a7 = __shfl_sync(0xffffffffu, alpha, t + 7);
            int j0 = __shfl_sync(0xffffffffu, j, t + 0);
            int j1 = __shfl_sync(0xffffffffu, j, t + 1);
            int j2 = __shfl_sync(0xffffffffu, j, t + 2);
            int j3 = __shfl_sync(0xffffffffu, j, t + 3);
            int j4 = __shfl_sync(0xffffffffu, j, t + 4);
            int j5 = __shfl_sync(0xffffffffu, j, t + 5);
            int j6 = __shfl_sync(0xffffffffu, j, t + 6);
            int j7 = __shfl_sync(0xffffffffu, j, t + 7);
            float x0 = xh[(size_t)j0 * HC + off];
            float x1 = xh[(size_t)j1 * HC + off];
            float x2 = xh[(size_t)j2 * HC + off];
            float x3 = xh[(size_t)j3 * HC + off];
            float x4 = xh[(size_t)j4 * HC + off];
            float x5 = xh[(size_t)j5 * HC + off];
            float x6 = xh[(size_t)j6 * HC + off];
            float x7 = xh[(size_t)j7 * HC + off];
            acc = fmaf(a0, x0, acc); acc = fmaf(a1, x1, acc);
            acc = fmaf(a2, x2, acc); acc = fmaf(a3, x3, acc);
            acc = fmaf(a4, x4, acc); acc = fmaf(a5, x5, acc);
            acc = fmaf(a6, x6, acc); acc = fmaf(a7, x7, acc);
        }
        for (; t < nn; t++) {
            float a = __shfl_sync(0xffffffffu, alpha, t);
            int jj  = __shfl_sync(0xffffffffu, j, t);
            acc = fmaf(a, xh[(size_t)jj * HC + off], acc);
        }
    }
#pragma unroll
    for (int off2 = 16; off2; off2 >>= 1)
        ds += __shfl_xor_sync(0xffffffffu, ds, off2);
    float dinv = 1.f / ds;
    g_v[(size_t)i * HC + off] = fmaf(acc, dinv, bias[off]);
}

// ---------------- K5: matvec, warp owns 4 channels exclusively ----------------
#define CHUNK 2048
__global__ __launch_bounds__(256) void k_matvec(const float* __restrict__ out_w) {
    __shared__ __align__(16) float sv[CHUNK];
    int k0 = blockIdx.x * CHUNK;
    int tid = threadIdx.x;
    int lane = tid & 31, wid = tid >> 5;
    const float4* v4 = (const float4*)&g_v[k0];
    float4* sv4 = (float4*)sv;
#pragma unroll
    for (int i = 0; i < CHUNK / 4 / 256; i++) sv4[tid + i * 256] = v4[tid + i * 256];
    __syncthreads();
    const float4* svc = (const float4*)sv;
#pragma unroll
    for (int cc = 0; cc < 4; cc++) {
        int c = wid * 4 + cc;
        const float4* w4 = (const float4*)(out_w + (size_t)c * VLEN + k0);
        float p0 = 0.f, p1 = 0.f;
#pragma unroll
        for (int i = 0; i < 8; i++) {      // 16 float4 per lane, 2-way ILP
            float4 w0 = w4[lane + (2 * i + 0) * 32];
            float4 w1 = w4[lane + (2 * i + 1) * 32];
            float4 v0 = svc[lane + (2 * i + 0) * 32];
            float4 v1 = svc[lane + (2 * i + 1) * 32];
            p0 = fmaf(w0.x, v0.x, p0); p0 = fmaf(w0.y, v0.y, p0);
            p0 = fmaf(w0.z, v0.z, p0); p0 = fmaf(w0.w, v0.w, p0);
            p1 = fmaf(w1.x, v1.x, p1); p1 = fmaf(w1.y, v1.y, p1);
            p1 = fmaf(w1.z, v1.z, p1); p1 = fmaf(w1.w, v1.w, p1);
        }
        float p = p0 + p1;
#pragma unroll
        for (int off = 16; off; off >>= 1) p += __shfl_down_sync(0xffffffffu, p, off);
        if (lane == 0) atomicAdd(&g_y[c], p);
    }
}

// ---------------- K6: softmax over 32 logits ----------------
__global__ void k_softmax(const float* __restrict__ out_b, float* __restrict__ out) {
    int t = threadIdx.x;  // 32 threads
    float v = g_y[t] + out_b[t];
    float mx = v;
#pragma unroll
    for (int off = 16; off; off >>= 1) mx = fmaxf(mx, __shfl_xor_sync(0xffffffffu, mx, off));
    float e = expf(v - mx);
    float ssum = e;
#pragma unroll
    for (int off = 16; off; off >>= 1) ssum += __shfl_xor_sync(0xffffffffu, ssum, off);
    out[t] = e / ssum;
}

// ---------------- launch ----------------
extern "C" void kernel_launch(void* const* d_in, const int* in_sizes, int n_in,
                              void* d_out, int out_size) {
    const float* x       = (const float*)d_in[0];
    const int*   ei      = (const int*)d_in[1];
    const float* lin_w   = (const float*)d_in[2];
    const float* att_src = (const float*)d_in[3];
    const float* att_dst = (const float*)d_in[4];
    const float* bias    = (const float*)d_in[5];
    const float* out_w   = (const float*)d_in[6];
    const float* out_b   = (const float*)d_in[7];
    float* out = (float*)d_out;

    k_zero<<<(N_NODES + 255) / 256, 256>>>();
    k_gemm<<<dim3(N_NODES / 64, HC / 64), 256>>>(x, lin_w, att_src, att_dst);
    k_scatter<<<E_EDGES / 2 / 256, 256>>>(ei);
    k_agg<<<N_NODES, 256>>>(bias);
    k_matvec<<<VLEN / CHUNK, 256>>>(out_w);
    k_softmax<<<1, 32>>>(out_b, out);
}